// round 1
// baseline (speedup 1.0000x reference)
#include <cuda_runtime.h>

// Problem dims (fixed by the dataset)
#define T_ 4
#define B_ 64
#define D_ 512
#define V_ 256
#define PLANE (B_*D_*V_)        // 8388608 elements per timestep
#define TOTAL (T_*PLANE)        // 33554432 elements per tensor

// Scratch (device globals — allocation-free per harness rules)
__device__ float g_qpre[TOTAL];
__device__ float g_kpre[TOTAL];
__device__ float g_obuf[TOTAL];

// ---------------------------------------------------------------------------
// Batched GEMM + folded BatchNorm epilogue.
// For batch z (= t*B + b): O[o,v] = BN( sum_d W[o,d] * X[d,v] )
// Tile: 64x64 output, K-chunk 16, 256 threads, 4x4 per thread.
// ---------------------------------------------------------------------------
__global__ void gemm_bn_kernel(const float* __restrict__ W,
                               const float* __restrict__ X,
                               const float* __restrict__ gamma,
                               const float* __restrict__ beta,
                               const float* __restrict__ mean,
                               const float* __restrict__ var,
                               float* __restrict__ O) {
    __shared__ __align__(16) float Ws[16][64];
    __shared__ __align__(16) float Xs[16][64];

    const int tid = threadIdx.x;
    const int v0  = blockIdx.x * 64;
    const int o0  = blockIdx.y * 64;
    const float* Xb = X + (size_t)blockIdx.z * D_ * V_;
    float*       Ob = O + (size_t)blockIdx.z * D_ * V_;

    const int tx = tid & 15;   // v micro-tile
    const int ty = tid >> 4;   // o micro-tile

    // load assignments
    const int wo = tid >> 2;          // 0..63  (o within tile)
    const int wd = (tid & 3) * 4;     // 0,4,8,12 (d within K chunk)
    const int xd = tid >> 4;          // 0..15  (d within K chunk)
    const int xv = (tid & 15) * 4;    // 0..60  (v within tile)

    float acc[4][4] = {};

    for (int k0 = 0; k0 < D_; k0 += 16) {
        float4 w4 = *(const float4*)&W[(size_t)(o0 + wo) * D_ + k0 + wd];
        Ws[wd + 0][wo] = w4.x;
        Ws[wd + 1][wo] = w4.y;
        Ws[wd + 2][wo] = w4.z;
        Ws[wd + 3][wo] = w4.w;
        *(float4*)&Xs[xd][xv] = *(const float4*)&Xb[(size_t)(k0 + xd) * V_ + v0 + xv];
        __syncthreads();

        #pragma unroll
        for (int kk = 0; kk < 16; ++kk) {
            float4 a4 = *(const float4*)&Ws[kk][ty * 4];
            float4 b4 = *(const float4*)&Xs[kk][tx * 4];
            float av[4] = {a4.x, a4.y, a4.z, a4.w};
            float bv[4] = {b4.x, b4.y, b4.z, b4.w};
            #pragma unroll
            for (int i = 0; i < 4; ++i)
                #pragma unroll
                for (int j = 0; j < 4; ++j)
                    acc[i][j] += av[i] * bv[j];
        }
        __syncthreads();
    }

    #pragma unroll
    for (int i = 0; i < 4; ++i) {
        const int o = o0 + ty * 4 + i;
        const float inv  = gamma[o] * rsqrtf(var[o] + 1e-5f);
        const float bias = beta[o] - mean[o] * inv;
        #pragma unroll
        for (int j = 0; j < 4; ++j) {
            Ob[(size_t)o * V_ + v0 + tx * 4 + j] = acc[i][j] * inv + bias;
        }
    }
}

// ---------------------------------------------------------------------------
// Fused: LIF(q_pre) -> per-head q_sum -> gate LIF(0.5) -> LIF(k_pre) -> gate*k
// One block per (b, h); 256 threads over v. All accesses fully coalesced.
// LIF: v = v + (x - v)/2 ; s = (v >= vth) ; v *= (1-s)   (hard reset to 0)
// ---------------------------------------------------------------------------
__global__ void lif_gate_kernel(const float* __restrict__ qpre,
                                const float* __restrict__ kpre,
                                float* __restrict__ out) {
    const int b = blockIdx.x;   // 0..63
    const int h = blockIdx.y;   // 0..3
    const int v = threadIdx.x;  // 0..255

    float qs[4] = {0.f, 0.f, 0.f, 0.f};

    // Pass 1: q LIF per channel, accumulate per-head spike sums for each t
    for (int i = 0; i < 128; ++i) {
        const int d = h * 128 + i;
        float vq = 0.f;
        #pragma unroll
        for (int t = 0; t < 4; ++t) {
            const size_t idx = (((size_t)t * B_ + b) * D_ + d) * V_ + v;
            const float xt = qpre[idx];
            vq += (xt - vq) * 0.5f;
            const float s = (vq >= 1.0f) ? 1.f : 0.f;
            qs[t] += s;
            vq *= (1.f - s);
        }
    }

    // Gate LIF on q_sum, threshold 0.5 (q_sum is an exact small integer in fp32)
    float gate[4];
    {
        float vg = 0.f;
        #pragma unroll
        for (int t = 0; t < 4; ++t) {
            vg += (qs[t] - vg) * 0.5f;
            const float s = (vg >= 0.5f) ? 1.f : 0.f;
            gate[t] = s;
            vg *= (1.f - s);
        }
    }

    // Pass 2: k LIF per channel, multiply by gate, write out
    for (int i = 0; i < 128; ++i) {
        const int d = h * 128 + i;
        float vk = 0.f;
        #pragma unroll
        for (int t = 0; t < 4; ++t) {
            const size_t idx = (((size_t)t * B_ + b) * D_ + d) * V_ + v;
            const float xt = kpre[idx];
            vk += (xt - vk) * 0.5f;
            const float s = (vk >= 1.f) ? 1.f : 0.f;
            out[idx] = gate[t] * s;
            vk *= (1.f - s);
        }
    }
}

// ---------------------------------------------------------------------------
// Final LIF (threshold 1.0) over the T axis, elementwise over one plane.
// ---------------------------------------------------------------------------
__global__ void lif_final_kernel(const float* __restrict__ pre,
                                 float* __restrict__ out) {
    const size_t idx = (size_t)blockIdx.x * blockDim.x + threadIdx.x;
    if (idx >= (size_t)PLANE) return;
    float v = 0.f;
    #pragma unroll
    for (int t = 0; t < 4; ++t) {
        const float xt = pre[(size_t)t * PLANE + idx];
        v += (xt - v) * 0.5f;
        const float s = (v >= 1.f) ? 1.f : 0.f;
        out[(size_t)t * PLANE + idx] = s;
        v *= (1.f - s);
    }
}

// ---------------------------------------------------------------------------
// kernel_launch
// Inputs (metadata order):
//  0 x, 1 Wq, 2 q_gamma, 3 q_beta, 4 q_mean, 5 q_var,
//  6 Wk, 7 k_gamma, 8 k_beta, 9 k_mean, 10 k_var,
// 11 Wp, 12 p_gamma, 13 p_beta, 14 p_mean, 15 p_var
// ---------------------------------------------------------------------------
extern "C" void kernel_launch(void* const* d_in, const int* in_sizes, int n_in,
                              void* d_out, int out_size) {
    const float* x  = (const float*)d_in[0];
    const float* Wq = (const float*)d_in[1];
    const float* qg = (const float*)d_in[2];
    const float* qb = (const float*)d_in[3];
    const float* qm = (const float*)d_in[4];
    const float* qv = (const float*)d_in[5];
    const float* Wk = (const float*)d_in[6];
    const float* kg = (const float*)d_in[7];
    const float* kb = (const float*)d_in[8];
    const float* km = (const float*)d_in[9];
    const float* kv = (const float*)d_in[10];
    const float* Wp = (const float*)d_in[11];
    const float* pg = (const float*)d_in[12];
    const float* pb = (const float*)d_in[13];
    const float* pm = (const float*)d_in[14];
    const float* pv = (const float*)d_in[15];
    float* out = (float*)d_out;

    float *qpre, *kpre, *obuf;
    cudaGetSymbolAddress((void**)&qpre, g_qpre);
    cudaGetSymbolAddress((void**)&kpre, g_kpre);
    cudaGetSymbolAddress((void**)&obuf, g_obuf);

    dim3 gg(V_ / 64, D_ / 64, T_ * B_);   // (4, 8, 256)

    gemm_bn_kernel<<<gg, 256>>>(Wq, x, qg, qb, qm, qv, qpre);
    gemm_bn_kernel<<<gg, 256>>>(Wk, x, kg, kb, km, kv, kpre);
    lif_gate_kernel<<<dim3(B_, 4), V_>>>(qpre, kpre, obuf);
    gemm_bn_kernel<<<gg, 256>>>(Wp, obuf, pg, pb, pm, pv, qpre);
    lif_final_kernel<<<(PLANE + 255) / 256, 256>>>(qpre, out);
}

// round 3
// speedup vs baseline: 5.5476x; 5.5476x over previous
#include <cuda_runtime.h>
#include <cuda_bf16.h>
#include <cstdint>

#define T_ 4
#define B_ 64
#define D_ 512
#define V_ 256
#define Z_ (T_*B_)            // 256 batches
#define TOTAL (Z_*D_*V_)      // 33554432 elements

// ---------------- scratch (device globals; allocation-free) ----------------
__device__ __nv_bfloat16 g_xt[TOTAL];     // x^T  : [z][v][d]
__device__ __nv_bfloat16 g_qpre[TOTAL];   // [z][v][o]  (reused for stage-3 pre)
__device__ __nv_bfloat16 g_kpre[TOTAL];   // [z][v][o]
__device__ __nv_bfloat16 g_obuf[TOTAL];   // gate*k spikes, [z][v][d]
__device__ __nv_bfloat16 g_wq[D_*D_];
__device__ __nv_bfloat16 g_wk[D_*D_];
__device__ __nv_bfloat16 g_wp[D_*D_];

// ---------------- helpers ----------------
__device__ __forceinline__ uint32_t smem_u32(const void* p) {
    uint32_t a;
    asm("{ .reg .u64 t; cvta.to.shared.u64 t, %1; cvt.u32.u64 %0, t; }" : "=r"(a) : "l"(p));
    return a;
}
__device__ __forceinline__ void cp16(uint32_t sdst, const void* gsrc) {
    asm volatile("cp.async.cg.shared.global [%0], [%1], 16;" :: "r"(sdst), "l"(gsrc) : "memory");
}
#define CP_COMMIT() asm volatile("cp.async.commit_group;" ::: "memory")
#define CP_WAIT1()  asm volatile("cp.async.wait_group 1;" ::: "memory")
#define CP_WAIT0()  asm volatile("cp.async.wait_group 0;" ::: "memory")

__device__ __forceinline__ void ldsm_x4(uint32_t* r, uint32_t addr) {
    asm volatile("ldmatrix.sync.aligned.m8n8.x4.shared.b16 {%0,%1,%2,%3}, [%4];"
        : "=r"(r[0]), "=r"(r[1]), "=r"(r[2]), "=r"(r[3]) : "r"(addr));
}
__device__ __forceinline__ void mma_bf16(float* d, const uint32_t* a, uint32_t b0, uint32_t b1) {
    asm volatile("mma.sync.aligned.m16n8k16.row.col.f32.bf16.bf16.f32 "
        "{%0,%1,%2,%3}, {%4,%5,%6,%7}, {%8,%9}, {%0,%1,%2,%3};"
        : "+f"(d[0]), "+f"(d[1]), "+f"(d[2]), "+f"(d[3])
        : "r"(a[0]), "r"(a[1]), "r"(a[2]), "r"(a[3]), "r"(b0), "r"(b1));
}

// ---------------------------------------------------------------------------
// bf16 mma.sync GEMM + folded BN:
//   O[z][v][o] = BN_o( sum_d A[z][v][d] * W[o][d] )
// CTA tile: M=128 (v), N=128 (o), K=512 in 16 chunks of 32. 8 warps, 64x32 each.
// SMEM pitch 40 bf16 (80B) -> ldmatrix bank-conflict-free.
// ---------------------------------------------------------------------------
#define KC 32
#define PITCH 40

__global__ void __launch_bounds__(256) gemm_bn_mma(
    const __nv_bfloat16* __restrict__ A,   // [Z][256][512]
    const __nv_bfloat16* __restrict__ W,   // [512][512]
    const float* __restrict__ gamma, const float* __restrict__ beta,
    const float* __restrict__ mean, const float* __restrict__ var,
    __nv_bfloat16* __restrict__ O)         // [Z][256][512]
{
    __shared__ __align__(16) __nv_bfloat16 sA[2][128 * PITCH];
    __shared__ __align__(16) __nv_bfloat16 sB[2][128 * PITCH];
    __shared__ float sScale[128], sBias[128];

    const int tid = threadIdx.x, wid = tid >> 5, lane = tid & 31;
    const int z = blockIdx.x, v0 = blockIdx.y * 128, o0 = blockIdx.z * 128;

    const __nv_bfloat16* Ab = A + ((size_t)z * V_ + v0) * D_;
    const __nv_bfloat16* Bb = W + (size_t)o0 * D_;

    if (tid < 128) {
        const float inv = gamma[o0 + tid] * rsqrtf(var[o0 + tid] + 1e-5f);
        sScale[tid] = inv;
        sBias[tid]  = beta[o0 + tid] - mean[o0 + tid] * inv;
    }

    const int lrow = tid >> 2;       // 0..63
    const int lcol = tid & 3;        // 0..3 (16B columns)
    const uint32_t sA0 = smem_u32(&sA[0][0]);
    const uint32_t sA1 = smem_u32(&sA[1][0]);
    const uint32_t sB0 = smem_u32(&sB[0][0]);
    const uint32_t sB1 = smem_u32(&sB[1][0]);

    // accumulators: [mt][nt][4]
    float acc[4][4][4];
    #pragma unroll
    for (int i = 0; i < 4; ++i)
        #pragma unroll
        for (int j = 0; j < 4; ++j)
            #pragma unroll
            for (int q = 0; q < 4; ++q) acc[i][j][q] = 0.f;

    const int wm = wid & 1;          // 0..1 : 64-row m slice
    const int wn = wid >> 1;         // 0..3 : 32-col n slice

    // issue loads for chunk kc into buffer buf
    auto issue_load = [&](int buf, int kc) {
        const uint32_t ab = buf ? sA1 : sA0;
        const uint32_t bb = buf ? sB1 : sB0;
        #pragma unroll
        for (int i = 0; i < 2; ++i) {
            const int row = lrow + i * 64;
            cp16(ab + row * 80 + lcol * 16, Ab + (size_t)row * D_ + kc + lcol * 8);
        }
        #pragma unroll
        for (int i = 0; i < 2; ++i) {
            const int row = lrow + i * 64;
            cp16(bb + row * 80 + lcol * 16, Bb + (size_t)row * D_ + kc + lcol * 8);
        }
        CP_COMMIT();
    };

    issue_load(0, 0);

    #pragma unroll 1
    for (int c = 0; c < 16; ++c) {
        if (c < 15) { issue_load((c + 1) & 1, (c + 1) * KC); CP_WAIT1(); }
        else        { CP_WAIT0(); }
        __syncthreads();

        const uint32_t aB = (c & 1) ? sA1 : sA0;
        const uint32_t bB = (c & 1) ? sB1 : sB0;

        #pragma unroll
        for (int kk = 0; kk < 2; ++kk) {
            uint32_t af[4][4];
            #pragma unroll
            for (int mt = 0; mt < 4; ++mt) {
                const int row = wm * 64 + mt * 16 + (lane & 15);
                ldsm_x4(af[mt], aB + row * 80 + kk * 32 + (lane >> 4) * 16);
            }
            uint32_t bf[2][4];
            #pragma unroll
            for (int np = 0; np < 2; ++np) {
                const int row = wn * 32 + np * 16 + (lane & 15);
                ldsm_x4(bf[np], bB + row * 80 + kk * 32 + (lane >> 4) * 16);
            }
            #pragma unroll
            for (int mt = 0; mt < 4; ++mt)
                #pragma unroll
                for (int nt = 0; nt < 4; ++nt) {
                    const int np = nt >> 1, hi = nt & 1;
                    mma_bf16(acc[mt][nt], af[mt], bf[np][hi ? 1 : 0], bf[np][hi ? 3 : 2]);
                }
        }
        __syncthreads();
    }

    // epilogue: BN -> bf16 pairs, direct stores (output [v][o], o contiguous)
    const int g  = lane >> 2;        // row within m16
    const int tg = lane & 3;         // col pair within n8
    #pragma unroll
    for (int mt = 0; mt < 4; ++mt) {
        #pragma unroll
        for (int nt = 0; nt < 4; ++nt) {
            const int oL = wn * 32 + nt * 8 + tg * 2;
            const float s0 = sScale[oL],     b0 = sBias[oL];
            const float s1 = sScale[oL + 1], b1 = sBias[oL + 1];
            #pragma unroll
            for (int h = 0; h < 2; ++h) {
                const int v = v0 + wm * 64 + mt * 16 + g + h * 8;
                const float fa = acc[mt][nt][2 * h]     * s0 + b0;
                const float fb = acc[mt][nt][2 * h + 1] * s1 + b1;
                const __nv_bfloat162 h2 = __floats2bfloat162_rn(fa, fb);
                *(uint32_t*)(O + ((size_t)z * V_ + v) * D_ + o0 + oL) = *(const uint32_t*)&h2;
            }
        }
    }
}

// ---------------------------------------------------------------------------
// x [z][d][v] fp32 -> xt [z][v][d] bf16 (32x32 smem transpose)
// ---------------------------------------------------------------------------
__global__ void transpose_x_kernel(const float* __restrict__ x, __nv_bfloat16* __restrict__ xt) {
    __shared__ float t[32][33];
    const int z = blockIdx.z, d0 = blockIdx.y * 32, v0 = blockIdx.x * 32;
    const int c = threadIdx.x & 31, r = threadIdx.x >> 5;
    const float* xp = x + ((size_t)z * D_ + d0) * V_ + v0;
    #pragma unroll
    for (int p = 0; p < 4; ++p) t[r + p * 8][c] = xp[(size_t)(r + p * 8) * V_ + c];
    __syncthreads();
    __nv_bfloat16* op = xt + ((size_t)z * V_ + v0) * D_ + d0;
    #pragma unroll
    for (int p = 0; p < 4; ++p) op[(size_t)(r + p * 8) * D_ + c] = __float2bfloat16(t[c][r + p * 8]);
}

__global__ void convert_w_kernel(const float* __restrict__ s, __nv_bfloat16* __restrict__ d) {
    const int i = blockIdx.x * 256 + threadIdx.x;
    d[i] = __float2bfloat16(s[i]);
}

// ---------------------------------------------------------------------------
// LIF(q) -> per-head q_sum -> gate LIF(0.5) -> LIF(k) -> out = gate*k
// Tensors [z][v][d] (d contiguous), z = t*B+b. Block = (v, b), 256 threads.
// ---------------------------------------------------------------------------
__global__ void lif_gate_kernel(const __nv_bfloat16* __restrict__ q,
                                const __nv_bfloat16* __restrict__ k,
                                __nv_bfloat16* __restrict__ out) {
    __shared__ float qs[4][4];   // [t][h]
    const int v = blockIdx.x, b = blockIdx.y;
    const int tid = threadIdx.x;
    if (tid < 16) ((float*)qs)[tid] = 0.f;
    __syncthreads();

    const int d1 = tid, d2 = tid + 256;
    const int w = tid >> 5, lane = tid & 31;
    const int h1 = w >> 2, h2 = 2 + (w >> 2);

#define IDX(t, d) ((((size_t)((t) * B_ + b)) * V_ + v) * D_ + (d))
    float s1[4], s2[4];
    {
        float vm = 0.f;
        #pragma unroll
        for (int t = 0; t < 4; ++t) {
            const float xt = __bfloat162float(q[IDX(t, d1)]);
            vm += (xt - vm) * 0.5f;
            s1[t] = (vm >= 1.f) ? 1.f : 0.f;
            vm *= (1.f - s1[t]);
        }
    }
    {
        float vm = 0.f;
        #pragma unroll
        for (int t = 0; t < 4; ++t) {
            const float xt = __bfloat162float(q[IDX(t, d2)]);
            vm += (xt - vm) * 0.5f;
            s2[t] = (vm >= 1.f) ? 1.f : 0.f;
            vm *= (1.f - s2[t]);
        }
    }
    #pragma unroll
    for (int t = 0; t < 4; ++t) {
        float a = s1[t], c2 = s2[t];
        #pragma unroll
        for (int off = 16; off > 0; off >>= 1) {
            a  += __shfl_down_sync(0xffffffffu, a,  off);
            c2 += __shfl_down_sync(0xffffffffu, c2, off);
        }
        if (lane == 0) { atomicAdd(&qs[t][h1], a); atomicAdd(&qs[t][h2], c2); }
    }
    __syncthreads();

    float g1[4], g2[4];
    {
        float vg = 0.f;
        #pragma unroll
        for (int t = 0; t < 4; ++t) {
            vg += (qs[t][h1] - vg) * 0.5f;
            g1[t] = (vg >= 0.5f) ? 1.f : 0.f;
            vg *= (1.f - g1[t]);
        }
    }
    {
        float vg = 0.f;
        #pragma unroll
        for (int t = 0; t < 4; ++t) {
            vg += (qs[t][h2] - vg) * 0.5f;
            g2[t] = (vg >= 0.5f) ? 1.f : 0.f;
            vg *= (1.f - g2[t]);
        }
    }
    {
        float vm = 0.f;
        #pragma unroll
        for (int t = 0; t < 4; ++t) {
            const float xt = __bfloat162float(k[IDX(t, d1)]);
            vm += (xt - vm) * 0.5f;
            const float s = (vm >= 1.f) ? 1.f : 0.f;
            out[IDX(t, d1)] = __float2bfloat16(g1[t] * s);
            vm *= (1.f - s);
        }
    }
    {
        float vm = 0.f;
        #pragma unroll
        for (int t = 0; t < 4; ++t) {
            const float xt = __bfloat162float(k[IDX(t, d2)]);
            vm += (xt - vm) * 0.5f;
            const float s = (vm >= 1.f) ? 1.f : 0.f;
            out[IDX(t, d2)] = __float2bfloat16(g2[t] * s);
            vm *= (1.f - s);
        }
    }
#undef IDX
}

// ---------------------------------------------------------------------------
// Final LIF(1.0) over t, input [z][v][o] bf16 -> output [t][b][o][v] fp32
// ---------------------------------------------------------------------------
__global__ void lif_final_kernel(const __nv_bfloat16* __restrict__ pre, float* __restrict__ out) {
    __shared__ float tile[32][33];
    const int o0 = blockIdx.x * 32, v0 = blockIdx.y * 32, b = blockIdx.z;
    const int ol = threadIdx.x & 31, vr = threadIdx.x >> 5;

    float spk[4][4];   // [pass][t]
    #pragma unroll
    for (int p = 0; p < 4; ++p) {
        const int vl = vr + p * 8;
        float vm = 0.f;
        #pragma unroll
        for (int t = 0; t < 4; ++t) {
            const size_t idx = (((size_t)(t * B_ + b)) * V_ + v0 + vl) * D_ + o0 + ol;
            const float xt = __bfloat162float(pre[idx]);
            vm += (xt - vm) * 0.5f;
            const float s = (vm >= 1.f) ? 1.f : 0.f;
            spk[p][t] = s;
            vm *= (1.f - s);
        }
    }
    #pragma unroll
    for (int t = 0; t < 4; ++t) {
        __syncthreads();
        #pragma unroll
        for (int p = 0; p < 4; ++p) tile[ol][vr + p * 8] = spk[p][t];
        __syncthreads();
        #pragma unroll
        for (int p = 0; p < 4; ++p) {
            const int orow = vr + p * 8;
            out[(((size_t)(t * B_ + b)) * D_ + o0 + orow) * V_ + v0 + ol] = tile[orow][ol];
        }
    }
}

// ---------------------------------------------------------------------------
extern "C" void kernel_launch(void* const* d_in, const int* in_sizes, int n_in,
                              void* d_out, int out_size) {
    const float* x  = (const float*)d_in[0];
    const float* Wq = (const float*)d_in[1];
    const float* qg = (const float*)d_in[2];
    const float* qb = (const float*)d_in[3];
    const float* qm = (const float*)d_in[4];
    const float* qv = (const float*)d_in[5];
    const float* Wk = (const float*)d_in[6];
    const float* kg = (const float*)d_in[7];
    const float* kb = (const float*)d_in[8];
    const float* km = (const float*)d_in[9];
    const float* kv = (const float*)d_in[10];
    const float* Wp = (const float*)d_in[11];
    const float* pg = (const float*)d_in[12];
    const float* pb = (const float*)d_in[13];
    const float* pm = (const float*)d_in[14];
    const float* pv = (const float*)d_in[15];
    float* out = (float*)d_out;

    __nv_bfloat16 *xt, *qp, *kp, *ob, *wq, *wk, *wp;
    cudaGetSymbolAddress((void**)&xt, g_xt);
    cudaGetSymbolAddress((void**)&qp, g_qpre);
    cudaGetSymbolAddress((void**)&kp, g_kpre);
    cudaGetSymbolAddress((void**)&ob, g_obuf);
    cudaGetSymbolAddress((void**)&wq, g_wq);
    cudaGetSymbolAddress((void**)&wk, g_wk);
    cudaGetSymbolAddress((void**)&wp, g_wp);

    convert_w_kernel<<<D_ * D_ / 256, 256>>>(Wq, wq);
    convert_w_kernel<<<D_ * D_ / 256, 256>>>(Wk, wk);
    convert_w_kernel<<<D_ * D_ / 256, 256>>>(Wp, wp);
    transpose_x_kernel<<<dim3(8, 16, Z_), 256>>>(x, xt);

    dim3 gg(Z_, V_ / 128, D_ / 128);   // (256, 2, 4)
    gemm_bn_mma<<<gg, 256>>>(xt, wq, qg, qb, qm, qv, qp);
    gemm_bn_mma<<<gg, 256>>>(xt, wk, kg, kb, km, kv, kp);
    lif_gate_kernel<<<dim3(V_, B_), 256>>>(qp, kp, ob);
    gemm_bn_mma<<<gg, 256>>>(ob, wp, pg, pb, pm, pv, qp);
    lif_final_kernel<<<dim3(16, 8, B_), 256>>>(qp, out);
}